// round 15
// baseline (speedup 1.0000x reference)
#include <cuda_runtime.h>

// Problem constants
#define BATCH 512
#define SEQ   1024
#define NTAG  50
#define TPAD  52          // padded tag count (multiple of 4)
#define BPB   2           // batches per block
#define NBLK  (BATCH / BPB)   // 256 blocks -> 2 per SM
#define NTHR  256             // 8 warps: per batch 2 fwd + 2 bwd (tag-split)
#define FULLM 0xffffffffu

// Scratch via __device__ globals (no allocs). Counter self-resets each run.
__device__ double g_partial[BATCH];
__device__ int    g_len[BATCH];
__device__ int    g_sched[BATCH];
__device__ unsigned int g_done = 0;

// ----------------------------- f32x2 helpers --------------------------------
typedef unsigned long long u64;

__device__ __forceinline__ u64 pk2(float lo, float hi) {
    u64 r; asm("mov.b64 %0,{%1,%2};" : "=l"(r) : "f"(lo), "f"(hi)); return r;
}
__device__ __forceinline__ void upk2(float& lo, float& hi, u64 v) {
    asm("mov.b64 {%0,%1},%2;" : "=f"(lo), "=f"(hi) : "l"(v));
}
__device__ __forceinline__ u64 fma2_(u64 a, u64 b, u64 c) {
    u64 d; asm("fma.rn.f32x2 %0,%1,%2,%3;" : "=l"(d) : "l"(a), "l"(b), "l"(c)); return d;
}

// Named barrier: syncs exactly `cnt` threads on barrier `id` (membar.cta incl.)
__device__ __forceinline__ void nbar(int id, int cnt) {
    asm volatile("bar.sync %0, %1;" :: "r"(id), "r"(cnt) : "memory");
}

// Accurate expf (init paths needing unbiased rounding): Cody-Waite + Horner.
__device__ __forceinline__ float exp_acc(float x) {
    float n = rintf(x * 1.4426950408889634f);
    float r = fmaf(n, -0.693359375f, x);
    r = fmaf(n, 2.1219444005469057e-4f, r);
    float p = 1.9841270e-4f;
    p = fmaf(p, r, 1.3888889e-3f);
    p = fmaf(p, r, 8.3333333e-3f);
    p = fmaf(p, r, 4.1666668e-2f);
    p = fmaf(p, r, 1.6666667e-1f);
    p = fmaf(p, r, 0.5f);
    p = fmaf(p, r, 1.0f);
    p = fmaf(p, r, 1.0f);
    return p * __int_as_float(((int)n + 127) << 23);
}

// Tags may be int32 (JAX w/o x64 silently downgrades int64) or genuine int64.
__device__ __forceinline__ int get_tag(const void* tags, int b, int t, int mode32) {
    if (mode32) return ((const int*)tags)[b * SEQ + t];
    return (int)((const long long*)tags)[b * SEQ + t];
}

__device__ __forceinline__ float warp_red_f(float v) {
    #pragma unroll
    for (int o = 16; o > 0; o >>= 1) v += __shfl_xor_sync(FULLM, v, o);
    return v;
}
__device__ __forceinline__ double warp_red_d(double v) {
    #pragma unroll
    for (int o = 16; o > 0; o >>= 1) v += __shfl_xor_sync(FULLM, v, o);
    return v;
}

// -------- fused prologue: binary-search lengths + bitonic sort + schedule ----
// mask is a prefix mask. One block, 512 threads. After sorting, block k gets
// slot0 = rank k and slot1 = rank 511-k (long paired with short).
__global__ void crf_sched_kernel(const int* __restrict__ mask) {
    __shared__ int keys[BATCH];
    const int tid = threadIdx.x;

    int a = 0, bb = SEQ;
    while (a < bb) {
        int m = (a + bb) >> 1;
        if (__ldg(mask + tid * SEQ + m)) a = m + 1; else bb = m;
    }
    g_len[tid] = a;
    keys[tid] = a * 1024 + tid;
    __syncthreads();

    for (int k = 2; k <= BATCH; k <<= 1) {
        for (int j = k >> 1; j > 0; j >>= 1) {
            int ixj = tid ^ j;
            if (ixj > tid) {
                int x = keys[tid], c = keys[ixj];
                bool up = ((tid & k) == 0);
                if (up ? (x < c) : (x > c)) { keys[tid] = c; keys[ixj] = x; }
            }
            __syncthreads();
        }
    }
    const int batch = keys[tid] & 1023;
    if (tid < 256) g_sched[tid * 2 + 0] = batch;
    else           g_sched[(511 - tid) * 2 + 1] = batch;
}

// Tag-split forward/backward: each chain direction is computed by TWO warps,
// each owning 25 of the 50 outputs (lane L of pair-warp p owns j = p*25+L).
// Per step per warp: 13 LDS.128 (shared alpha) + 25 fma2 + scalar epilogue +
// STS.32 + named bar.sync(64). den = log sum_i alpha_M[i]*beta_M[i]; exact
// pow2 renorm every 4 steps (pivot alpha[0], both pair warps fold same fac).
__global__ void __launch_bounds__(NTHR, 1) crf_main_kernel(
    const float* __restrict__ ts,          // [B,S,T] token_scores
    const void*  __restrict__ tags_raw,    // [B,S] int32 OR int64
    const int*   __restrict__ mask,        // [B,S]
    const float* __restrict__ trans,       // [T,T]
    const float* __restrict__ startt,      // [T]
    const float* __restrict__ endt,        // [T]
    float* __restrict__ out)               // [1]
{
    const int w    = threadIdx.x >> 5;      // 0..7 ; SMSP = w%4
    const int lane = threadIdx.x & 31;
    const int bq   = w >> 2;                // batch slot (0 long, 1 short)
    const int dir  = (w >> 1) & 1;          // 0 = fwd, 1 = bwd
    const int p    = w & 1;                 // pair index within direction
    const int b    = g_sched[blockIdx.x * BPB + bq];
    const int owner = (lane < 25);
    const int j    = p * 25 + (lane < 25 ? lane : 24);   // owned output (clamped)
    const int barid = 1 + bq * 2 + dir;     // named barrier per (batch,dir)

    __shared__ __align__(16) float afb[BPB][2][TPAD];   // fwd alpha buffers
    __shared__ __align__(16) float cbb[BPB][2][TPAD];   // bwd c buffers
    __shared__ float  betaf[BPB][TPAD];                 // final raw beta_M
    __shared__ float  num_sh[BPB];
    __shared__ int    sEb_sh[BPB];
    __shared__ double red_sh[NTHR];
    __shared__ unsigned int is_last;

    const float* tsb = ts + (size_t)b * SEQ * NTAG;

    const int len = g_len[b];          // >= 1
    const int M   = len >> 1;          // meet point
    const int nb  = len - 1 - M;       // backward step count

    int sumEf = 0, curf = 0;           // fwd state

    if (dir == 0) {
        // =================== FORWARD PAIR-WARP ===================
        // E pairs along inputs for owned output j: E[q]=(E[2q][j],E[2q+1][j])
        u64 E[25];
        #pragma unroll
        for (int q = 0; q < 25; q++) {
            float elo = 0.f, ehi = 0.f;
            if (owner) {
                elo = __expf(__ldg(trans + (2 * q)     * NTAG + j));
                ehi = __expf(__ldg(trans + (2 * q + 1) * NTAG + j));
            }
            E[q] = pk2(elo, ehi);
        }

        float* a0f = afb[bq][0];
        float* a1f = afb[bq][1];
        if (owner)
            a0f[j] = exp_acc(__ldg(startt + j) + tsb[j]);
        if (p == 0 && lane == 25) {
            a0f[50] = 0.f; a0f[51] = 0.f; a1f[50] = 0.f; a1f[51] = 0.f;
        }
        nbar(barid, 64);

        const int lenf = M + 1;        // steps t = 1..M

        float xb[8];
        #pragma unroll
        for (int k = 0; k < 8; k++) {
            int t = 1 + k; if (t > SEQ - 1) t = SEQ - 1;
            xb[k] = __ldg(tsb + (size_t)t * NTAG + j);
        }

        auto fstep = [&](float x, bool renorm) {
            float exs = __expf(x);
            const float* af = afb[bq][curf];
            const ulonglong2* av = (const ulonglong2*)af;
            float* an = afb[bq][curf ^ 1];
            if (renorm) {
                int eb = (__float_as_int(af[0]) >> 23) & 255;
                sumEf += eb - 127;
                exs *= __int_as_float((254 - eb) << 23);   // 2^{-e}, exact
            }
            u64 c0 = 0, c1 = 0, c3 = 0;
            #pragma unroll
            for (int qq = 0; qq < 13; qq++) {
                ulonglong2 v = av[qq];
                c0 = fma2_(v.x, E[2 * qq >= 25 ? 24 : 2 * qq], c0);
                if (2 * qq + 1 < 25) {
                    if (qq & 1) c3 = fma2_(v.y, E[2 * qq + 1], c3);
                    else        c1 = fma2_(v.y, E[2 * qq + 1], c1);
                }
            }
            // note: qq=12 -> v.x = inputs (48,49) = pair 24 ; v.y = pad (zero)
            float plo, phi, qlo, qhi, rlo, rhi;
            upk2(plo, phi, c0); upk2(qlo, qhi, c1); upk2(rlo, rhi, c3);
            float dot = ((plo + phi) + (qlo + qhi)) + (rlo + rhi);
            float anew = dot * exs;
            if (owner) an[j] = anew;
            curf ^= 1;
            nbar(barid, 64);
        };

        int tb = 1;
        for (; tb + 7 < lenf; tb += 8) {
            float xn[8];
            #pragma unroll
            for (int k = 0; k < 8; k++) {
                int t = tb + 8 + k; if (t > SEQ - 1) t = SEQ - 1;
                xn[k] = __ldg(tsb + (size_t)t * NTAG + j);
            }
            #pragma unroll
            for (int k = 0; k < 8; k++)
                fstep(xb[k], (k & 3) == 0);
            #pragma unroll
            for (int k = 0; k < 8; k++) xb[k] = xn[k];
        }
        for (int t = tb; t < lenf; t++)
            fstep(xb[t - tb], (t & 3) == 1);
    } else {
        // =================== BACKWARD PAIR-WARP ===================
        int sumEb = 0;

        if (nb == 0) {
            if (owner)
                betaf[bq][j] = exp_acc(__ldg(endt + j));
        } else {
            // E pairs along inputs for owned row j: ER[q]=(E[j][2q],E[j][2q+1])
            u64 ER[25];
            #pragma unroll
            for (int q = 0; q < 25; q++) {
                float elo = 0.f, ehi = 0.f;
                if (owner) {
                    elo = __expf(__ldg(trans + j * NTAG + 2 * q));
                    ehi = __expf(__ldg(trans + j * NTAG + 2 * q + 1));
                }
                ER[q] = pk2(elo, ehi);
            }

            float* c0f = cbb[bq][0];
            float* c1f = cbb[bq][1];
            if (owner)
                c0f[j] = exp_acc(tsb[(size_t)(len - 1) * NTAG + j] + __ldg(endt + j));
            if (p == 0 && lane == 25) {
                c0f[50] = 0.f; c0f[51] = 0.f; c1f[50] = 0.f; c1f[51] = 0.f;
            }
            nbar(barid, 64);

            int curb = 0;
            const int nbm1 = nb - 1;   // normal steps; last step stores raw

            float xb[8];
            #pragma unroll
            for (int k = 0; k < 8; k++) {
                int t = len - 2 - k; if (t < 0) t = 0;
                xb[k] = __ldg(tsb + (size_t)t * NTAG + j);
            }

            auto bstep = [&](float x, bool renorm, bool fin) {
                float exs = __expf(x);
                const float* cf = cbb[bq][curb];
                const ulonglong2* cv = (const ulonglong2*)cf;
                float* cn = cbb[bq][curb ^ 1];
                if (renorm) {
                    int eb = (__float_as_int(cf[0]) >> 23) & 255;
                    sumEb += eb - 127;
                    exs *= __int_as_float((254 - eb) << 23);
                }
                u64 c0 = 0, c1 = 0, c3 = 0;
                #pragma unroll
                for (int qq = 0; qq < 13; qq++) {
                    ulonglong2 v = cv[qq];
                    c0 = fma2_(v.x, ER[2 * qq >= 25 ? 24 : 2 * qq], c0);
                    if (2 * qq + 1 < 25) {
                        if (qq & 1) c3 = fma2_(v.y, ER[2 * qq + 1], c3);
                        else        c1 = fma2_(v.y, ER[2 * qq + 1], c1);
                    }
                }
                float plo, phi, qlo, qhi, rlo, rhi;
                upk2(plo, phi, c0); upk2(qlo, qhi, c1); upk2(rlo, rhi, c3);
                float dot = ((plo + phi) + (qlo + qhi)) + (rlo + rhi);
                if (fin) {
                    if (owner) betaf[bq][j] = dot;
                } else {
                    if (owner) cn[j] = dot * exs;
                }
                curb ^= 1;
                nbar(barid, 64);
            };

            int idx = 0;
            for (; idx + 7 < nbm1; idx += 8) {
                float xn[8];
                #pragma unroll
                for (int k = 0; k < 8; k++) {
                    int t = len - 2 - (idx + 8 + k); if (t < 0) t = 0;
                    xn[k] = __ldg(tsb + (size_t)t * NTAG + j);
                }
                #pragma unroll
                for (int k = 0; k < 8; k++)
                    bstep(xb[k], (k & 3) == 0, false);
                #pragma unroll
                for (int k = 0; k < 8; k++) xb[k] = xn[k];
            }
            for (int k = 0; idx < nbm1; idx++, k++)
                bstep(xb[k], (idx & 3) == 0, false);

            bstep(0.f, false, true);       // final: store raw beta_M
        }

        if (p == 0 && lane == 0) sEb_sh[bq] = sumEb;

        if (p == 1) {
            // ---- numerator + dtype detection (off critical path, 2nd warp)
            int any_hi = 0;
            {
                const u64* p64 = (const u64*)tags_raw;
                #pragma unroll
                for (int i = 0; i < 16; i++) any_hi |= (int)(p64[i] >> 32);
            }
            const int mode32 = (any_hi != 0);

            float nsum = 0.f;
            for (int t = lane; t < len; t += 32) {
                int tg = get_tag(tags_raw, b, t, mode32);
                nsum += __ldg(tsb + t * NTAG + tg);
                if (t > 0) {
                    int tp = get_tag(tags_raw, b, t - 1, mode32);
                    nsum += __ldg(trans + tp * NTAG + tg);
                }
            }
            if (lane == 0)
                nsum += __ldg(startt + get_tag(tags_raw, b, 0, mode32))
                      + __ldg(endt   + get_tag(tags_raw, b, len - 1, mode32));
            nsum = warp_red_f(nsum);
            if (lane == 0) num_sh[bq] = nsum;
        }
    }

    // ---------------- combine: den = ln2*(sEf+sEb) + log(sum alpha*beta) ----
    __syncthreads();
    if (dir == 0 && p == 0) {
        const float* af = afb[bq][curf];
        double part = 0.0;
        if (owner) {
            part = (double)af[lane]      * (double)betaf[bq][lane]
                 + (double)af[lane + 25] * (double)betaf[bq][lane + 25];
        }
        part = warp_red_d(part);
        if (lane == 0) {
            double den = (double)(sumEf + sEb_sh[bq]) * 0.6931471805599453
                       + log(part);
            g_partial[b] = den - (double)num_sh[bq];
        }
    }

    // ---------------- last-block final reduction (deterministic) ----------
    __syncthreads();
    __threadfence();
    if (threadIdx.x == 0)
        is_last = (atomicAdd(&g_done, 1u) == (unsigned)(NBLK - 1));
    __syncthreads();
    if (is_last) {
        const int tid = threadIdx.x;           // 256 threads, 512 partials
        double s = g_partial[tid] + g_partial[tid + NTHR];
        red_sh[tid] = s;
        __syncthreads();
        #pragma unroll
        for (int o = 128; o > 0; o >>= 1) {
            if (tid < o) red_sh[tid] += red_sh[tid + o];
            __syncthreads();
        }
        if (tid == 0) {
            out[0] = (float)(red_sh[0] * (1.0 / (double)BATCH));
            g_done = 0;                        // reset for next graph replay
        }
    }
}

extern "C" void kernel_launch(void* const* d_in, const int* in_sizes, int n_in,
                              void* d_out, int out_size)
{
    const float* token_scores = (const float*)d_in[0];
    const void*  tags         = (const void*)d_in[1];
    const int*   token_mask   = (const int*)d_in[2];
    const float* transitions  = (const float*)d_in[3];
    const float* start_trans  = (const float*)d_in[4];
    const float* end_trans    = (const float*)d_in[5];
    float* out = (float*)d_out;

    crf_sched_kernel<<<1, BATCH>>>(token_mask);
    crf_main_kernel<<<NBLK, NTHR>>>(token_scores, tags, token_mask,
                                    transitions, start_trans, end_trans, out);
}

// round 16
// speedup vs baseline: 2.0674x; 2.0674x over previous
#include <cuda_runtime.h>

// Problem constants
#define BATCH 512
#define SEQ   1024
#define NTAG  50
#define TPAD  52          // padded tag count (multiple of 4)
#define BPB   4           // batches per block
#define NBLK  (BATCH / BPB)
#define NTHR  256         // 8 warps: w<4 fwd, w>=4 bwd; wid%4 = SMSP pairing
#define FULLM 0xffffffffu

// Scratch via __device__ globals (no allocs). Counter self-resets each run.
__device__ double g_partial[BATCH];
__device__ int    g_len[BATCH];
__device__ int    g_sched[BATCH];
__device__ unsigned int g_done = 0;

// ----------------------------- f32x2 helpers --------------------------------
typedef unsigned long long u64;

__device__ __forceinline__ u64 pk2(float lo, float hi) {
    u64 r; asm("mov.b64 %0,{%1,%2};" : "=l"(r) : "f"(lo), "f"(hi)); return r;
}
__device__ __forceinline__ void upk2(float& lo, float& hi, u64 v) {
    asm("mov.b64 {%0,%1},%2;" : "=f"(lo), "=f"(hi) : "l"(v));
}
__device__ __forceinline__ u64 fma2_(u64 a, u64 b, u64 c) {
    u64 d; asm("fma.rn.f32x2 %0,%1,%2,%3;" : "=l"(d) : "l"(a), "l"(b), "l"(c)); return d;
}
__device__ __forceinline__ u64 mul2_(u64 a, u64 b) {
    u64 d; asm("mul.rn.f32x2 %0,%1,%2;" : "=l"(d) : "l"(a), "l"(b)); return d;
}
__device__ __forceinline__ u64 add2_(u64 a, u64 b) {
    u64 d; asm("add.rn.f32x2 %0,%1,%2;" : "=l"(d) : "l"(a), "l"(b)); return d;
}

// Accurate expf (init paths needing unbiased rounding): Cody-Waite + Horner.
__device__ __forceinline__ float exp_acc(float x) {
    float n = rintf(x * 1.4426950408889634f);
    float r = fmaf(n, -0.693359375f, x);
    r = fmaf(n, 2.1219444005469057e-4f, r);
    float p = 1.9841270e-4f;
    p = fmaf(p, r, 1.3888889e-3f);
    p = fmaf(p, r, 8.3333333e-3f);
    p = fmaf(p, r, 4.1666668e-2f);
    p = fmaf(p, r, 1.6666667e-1f);
    p = fmaf(p, r, 0.5f);
    p = fmaf(p, r, 1.0f);
    p = fmaf(p, r, 1.0f);
    return p * __int_as_float(((int)n + 127) << 23);
}

// Cheap packed exp for per-step emissions (MUFU.EX2 path, ample accuracy margin).
__device__ __forceinline__ u64 pexpf2(u64 x2) {
    float x0, x1; upk2(x0, x1, x2);
    return pk2(__expf(x0), __expf(x1));
}

// Tags may be int32 (JAX w/o x64 silently downgrades int64) or genuine int64.
__device__ __forceinline__ int get_tag(const void* tags, int b, int t, int mode32) {
    if (mode32) return ((const int*)tags)[b * SEQ + t];
    return (int)((const long long*)tags)[b * SEQ + t];
}

__device__ __forceinline__ float warp_red_f(float v) {
    #pragma unroll
    for (int o = 16; o > 0; o >>= 1) v += __shfl_xor_sync(FULLM, v, o);
    return v;
}
__device__ __forceinline__ double warp_red_d(double v) {
    #pragma unroll
    for (int o = 16; o > 0; o >>= 1) v += __shfl_xor_sync(FULLM, v, o);
    return v;
}

// -------- fused prologue: binary-search lengths + bitonic sort + schedule ----
__global__ void crf_sched_kernel(const int* __restrict__ mask) {
    __shared__ int keys[BATCH];
    const int tid = threadIdx.x;

    // binary search: first zero index == len (all-ones -> 1024)
    int a = 0, bb = SEQ;
    while (a < bb) {
        int m = (a + bb) >> 1;
        if (__ldg(mask + tid * SEQ + m)) a = m + 1; else bb = m;
    }
    g_len[tid] = a;
    keys[tid] = a * 1024 + tid;
    __syncthreads();

    for (int k = 2; k <= BATCH; k <<= 1) {
        for (int j = k >> 1; j > 0; j >>= 1) {
            int ixj = tid ^ j;
            if (ixj > tid) {
                int x = keys[tid], c = keys[ixj];
                bool up = ((tid & k) == 0);
                if (up ? (x < c) : (x > c)) { keys[tid] = c; keys[ixj] = x; }
            }
            __syncthreads();
        }
    }
    const int batch = keys[tid] & 1023;
    int k2, q;
    if (tid < 256)       { k2 = tid >> 1;         q = (tid & 1) ? 2 : 0; }
    else if (tid & 1)    { k2 = (511 - tid) >> 1; q = 1; }
    else                 { k2 = (510 - tid) >> 1; q = 3; }
    g_sched[k2 * 4 + q] = batch;
}

// Forward/backward split: den = log sum_i alpha_M[i] * beta_M[i].
// fwd warps (w<4) handle slot w; bwd warps (w>=4) handle slot perm[w-4],
// perm = (1,0,3,2)  =>  each SMSP gets fwd(long)+bwd(short) or vice versa.
// Scaled-linear domain, exact pow2 renorm every 4 steps, emission prefetch 8.
// Change vs the 86.7us kernel: v.x accumulation split across c[0]/c[2] by
// compile-time q parity (depth 13 -> 7), roles static per instruction.
__global__ void __launch_bounds__(NTHR, 1) crf_main_kernel(
    const float* __restrict__ ts,          // [B,S,T] token_scores
    const void*  __restrict__ tags_raw,    // [B,S] int32 OR int64
    const int*   __restrict__ mask,        // [B,S] int32 (prefix mask)
    const float* __restrict__ trans,       // [T,T]
    const float* __restrict__ startt,      // [T]
    const float* __restrict__ endt,        // [T]
    float* __restrict__ out)               // [1]
{
    const int w    = threadIdx.x >> 5;
    const int lane = threadIdx.x & 31;
    const int dir  = w >> 2;                // 0 = fwd, 1 = bwd
    const int bperm[4] = {1, 0, 3, 2};
    const int bq   = (dir == 0) ? (w & 3) : bperm[w & 3];   // slot in block
    const int b    = g_sched[blockIdx.x * BPB + bq];        // scheduled batch
    const int owner = (lane < 25);
    const int j0 = 2 * lane, j1 = 2 * lane + 1;

    __shared__ __align__(16) float afb[BPB][2][TPAD];   // fwd alpha buffers
    __shared__ __align__(16) float cbb[BPB][2][TPAD];   // bwd c buffers
    __shared__ float  betaf[BPB][TPAD];                 // final raw beta_M
    __shared__ float  num_sh[BPB];
    __shared__ int    sEb_sh[BPB];
    __shared__ double red_sh[NTHR];
    __shared__ unsigned int is_last;

    const float* tsb = ts + (size_t)b * SEQ * NTAG;

    const int len = g_len[b];          // >= 1
    const int M   = len >> 1;          // meet point
    const int nb  = len - 1 - M;       // backward step count

    int sumEf = 0, curf = 0;           // fwd state (live only in fwd warps)

    if (dir == 0) {
        // =================== FORWARD WARP ===================
        u64 E0[26], E1[26];
        #pragma unroll
        for (int q = 0; q < 26; q++) {
            float e00 = 0.f, e01 = 0.f, e10 = 0.f, e11 = 0.f;
            if (owner) {
                int i0 = 2 * q, i1 = 2 * q + 1;
                if (i0 < NTAG) {
                    e00 = exp_acc(__ldg(trans + i0 * NTAG + j0));
                    e10 = exp_acc(__ldg(trans + i0 * NTAG + j1));
                }
                if (i1 < NTAG) {
                    e01 = exp_acc(__ldg(trans + i1 * NTAG + j0));
                    e11 = exp_acc(__ldg(trans + i1 * NTAG + j1));
                }
            }
            E0[q] = pk2(e00, e01);
            E1[q] = pk2(e10, e11);
        }

        float* a0f = afb[bq][0];
        float* a1f = afb[bq][1];
        if (owner) {
            a0f[j0] = exp_acc(__ldg(startt + j0) + tsb[j0]);
            a0f[j1] = exp_acc(__ldg(startt + j1) + tsb[j1]);
        }
        if (lane == 25) {
            a0f[50] = 0.f; a0f[51] = 0.f; a1f[50] = 0.f; a1f[51] = 0.f;
        }
        __syncwarp();

        const int lenf = M + 1;        // steps t = 1..M

        u64 xb[8];
        #pragma unroll
        for (int k = 0; k < 8; k++) {
            int t = 1 + k; if (t > SEQ - 1) t = SEQ - 1;
            xb[k] = owner ? __ldg((const u64*)(tsb + (size_t)t * NTAG + j0)) : 0ull;
        }

        auto fstep = [&](u64 ex, bool renorm) {
            const float* af = afb[bq][curf];
            const ulonglong2* av = (const ulonglong2*)af;
            float* an = afb[bq][curf ^ 1];
            if (renorm) {
                int eb = (__float_as_int(af[0]) >> 23) & 255;
                sumEf += eb - 127;
                float fac = __int_as_float((254 - eb) << 23);   // 2^{-e}, exact
                ex = mul2_(ex, pk2(fac, fac));
            }
            u64 c0[4] = {0,0,0,0}, c1[4] = {0,0,0,0};
            #pragma unroll
            for (int q = 0; q < 13; q++) {
                ulonglong2 v = av[q];
                c0[q & 1 ? 2 : 0] = fma2_(v.x, E0[2 * q],     c0[q & 1 ? 2 : 0]);
                c0[q & 1 ? 3 : 1] = fma2_(v.y, E0[2 * q + 1], c0[q & 1 ? 3 : 1]);
                c1[q & 1 ? 2 : 0] = fma2_(v.x, E1[2 * q],     c1[q & 1 ? 2 : 0]);
                c1[q & 1 ? 3 : 1] = fma2_(v.y, E1[2 * q + 1], c1[q & 1 ? 3 : 1]);
            }
            u64 s0 = add2_(add2_(c0[0], c0[1]), add2_(c0[2], c0[3]));
            u64 s1 = add2_(add2_(c1[0], c1[1]), add2_(c1[2], c1[3]));
            float p0, q0, p1, q1;
            upk2(p0, q0, s0); upk2(p1, q1, s1);
            u64 anew = mul2_(pk2(p0 + q0, p1 + q1), ex);
            if (owner) *(u64*)(an + j0) = anew;
            curf ^= 1;
            __syncwarp();
        };

        int tb = 1;
        for (; tb + 7 < lenf; tb += 8) {
            u64 xn[8];
            #pragma unroll
            for (int k = 0; k < 8; k++) {
                int t = tb + 8 + k; if (t > SEQ - 1) t = SEQ - 1;
                xn[k] = owner ? __ldg((const u64*)(tsb + (size_t)t * NTAG + j0)) : 0ull;
            }
            #pragma unroll
            for (int k = 0; k < 8; k++)
                fstep(pexpf2(xb[k]), (k & 3) == 0);
            #pragma unroll
            for (int k = 0; k < 8; k++) xb[k] = xn[k];
        }
        for (int t = tb; t < lenf; t++)
            fstep(pexpf2(xb[t - tb]), (t & 3) == 1);
    } else {
        // =================== BACKWARD WARP ===================
        int any_hi = 0;
        {
            const u64* p64 = (const u64*)tags_raw;
            #pragma unroll
            for (int i = 0; i < 16; i++) any_hi |= (int)(p64[i] >> 32);
        }
        const int mode32 = (any_hi != 0);

        // Numerator (gold-path score).
        float nsum = 0.f;
        for (int t = lane; t < len; t += 32) {
            int tg = get_tag(tags_raw, b, t, mode32);
            nsum += __ldg(tsb + t * NTAG + tg);
            if (t > 0) {
                int tp = get_tag(tags_raw, b, t - 1, mode32);
                nsum += __ldg(trans + tp * NTAG + tg);
            }
        }
        if (lane == 0)
            nsum += __ldg(startt + get_tag(tags_raw, b, 0, mode32))
                  + __ldg(endt   + get_tag(tags_raw, b, len - 1, mode32));
        nsum = warp_red_f(nsum);
        if (lane == 0) num_sh[bq] = nsum;

        int sumEb = 0;

        if (nb == 0) {
            if (owner) {
                betaf[bq][j0] = exp_acc(__ldg(endt + j0));
                betaf[bq][j1] = exp_acc(__ldg(endt + j1));
            }
        } else {
            u64 ER0[26], ER1[26];
            #pragma unroll
            for (int q = 0; q < 26; q++) {
                float e00 = 0.f, e01 = 0.f, e10 = 0.f, e11 = 0.f;
                if (owner) {
                    int c0 = 2 * q, c1 = 2 * q + 1;
                    if (c0 < NTAG) {
                        e00 = exp_acc(__ldg(trans + j0 * NTAG + c0));
                        e10 = exp_acc(__ldg(trans + j1 * NTAG + c0));
                    }
                    if (c1 < NTAG) {
                        e01 = exp_acc(__ldg(trans + j0 * NTAG + c1));
                        e11 = exp_acc(__ldg(trans + j1 * NTAG + c1));
                    }
                }
                ER0[q] = pk2(e00, e01);
                ER1[q] = pk2(e10, e11);
            }

            float* c0f = cbb[bq][0];
            float* c1f = cbb[bq][1];
            if (owner) {   // c_j = exp(x_{len-1}[j] + end_j)
                c0f[j0] = exp_acc(tsb[(size_t)(len - 1) * NTAG + j0] + __ldg(endt + j0));
                c0f[j1] = exp_acc(tsb[(size_t)(len - 1) * NTAG + j1] + __ldg(endt + j1));
            }
            if (lane == 25) {
                c0f[50] = 0.f; c0f[51] = 0.f; c1f[50] = 0.f; c1f[51] = 0.f;
            }
            __syncwarp();

            int curb = 0;
            const int nbm1 = nb - 1;   // normal steps; last step stores raw

            u64 xb[8];
            #pragma unroll
            for (int k = 0; k < 8; k++) {
                int t = len - 2 - k; if (t < 0) t = 0;
                xb[k] = owner ? __ldg((const u64*)(tsb + (size_t)t * NTAG + j0)) : 0ull;
            }

            auto bstep = [&](u64 ex, bool renorm, bool fin) {
                const float* cf = cbb[bq][curb];
                const ulonglong2* cv = (const ulonglong2*)cf;
                float* cn = cbb[bq][curb ^ 1];
                if (renorm) {
                    int eb = (__float_as_int(cf[0]) >> 23) & 255;
                    sumEb += eb - 127;
                    float fac = __int_as_float((254 - eb) << 23);
                    ex = mul2_(ex, pk2(fac, fac));
                }
                u64 c0[4] = {0,0,0,0}, c1[4] = {0,0,0,0};
                #pragma unroll
                for (int q = 0; q < 13; q++) {
                    ulonglong2 v = cv[q];
                    c0[q & 1 ? 2 : 0] = fma2_(v.x, ER0[2 * q],     c0[q & 1 ? 2 : 0]);
                    c0[q & 1 ? 3 : 1] = fma2_(v.y, ER0[2 * q + 1], c0[q & 1 ? 3 : 1]);
                    c1[q & 1 ? 2 : 0] = fma2_(v.x, ER1[2 * q],     c1[q & 1 ? 2 : 0]);
                    c1[q & 1 ? 3 : 1] = fma2_(v.y, ER1[2 * q + 1], c1[q & 1 ? 3 : 1]);
                }
                u64 s0 = add2_(add2_(c0[0], c0[1]), add2_(c0[2], c0[3]));
                u64 s1 = add2_(add2_(c1[0], c1[1]), add2_(c1[2], c1[3]));
                float p0, q0, p1, q1;
                upk2(p0, q0, s0); upk2(p1, q1, s1);
                if (fin) {
                    if (owner) {
                        betaf[bq][j0] = p0 + q0;
                        betaf[bq][j1] = p1 + q1;
                    }
                } else {
                    u64 cnew = mul2_(pk2(p0 + q0, p1 + q1), ex);
                    if (owner) *(u64*)(cn + j0) = cnew;
                }
                curb ^= 1;
                __syncwarp();
            };

            int idx = 0;
            for (; idx + 7 < nbm1; idx += 8) {
                u64 xn[8];
                #pragma unroll
                for (int k = 0; k < 8; k++) {
                    int t = len - 2 - (idx + 8 + k); if (t < 0) t = 0;
                    xn[k] = owner ? __ldg((const u64*)(tsb + (size_t)t * NTAG + j0)) : 0ull;
                }
                #pragma unroll
                for (int k = 0; k < 8; k++)
                    bstep(pexpf2(xb[k]), (k & 3) == 0, false);
                #pragma unroll
                for (int k = 0; k < 8; k++) xb[k] = xn[k];
            }
            for (int k = 0; idx < nbm1; idx++, k++)
                bstep(pexpf2(xb[k]), (idx & 3) == 0, false);

            bstep(0ull, false, true);      // final: store raw beta_M
        }

        if (lane == 0) sEb_sh[bq] = sumEb;
    }

    // ---------------- combine: den = ln2*(sEf+sEb) + log(sum alpha*beta) ----
    __syncthreads();
    if (dir == 0) {
        double part = 0.0;
        if (owner) {
            const float* af = afb[bq][curf];
            part = (double)af[j0] * (double)betaf[bq][j0]
                 + (double)af[j1] * (double)betaf[bq][j1];
        }
        part = warp_red_d(part);
        if (lane == 0) {
            double den = (double)(sumEf + sEb_sh[bq]) * 0.6931471805599453
                       + log(part);
            g_partial[b] = den - (double)num_sh[bq];
        }
    }

    // ---------------- last-block final reduction (deterministic) ----------
    __syncthreads();
    __threadfence();
    if (threadIdx.x == 0)
        is_last = (atomicAdd(&g_done, 1u) == (unsigned)(NBLK - 1));
    __syncthreads();
    if (is_last) {
        const int tid = threadIdx.x;           // 256 threads, 512 partials
        double s = g_partial[tid] + g_partial[tid + NTHR];
        red_sh[tid] = s;
        __syncthreads();
        #pragma unroll
        for (int o = 128; o > 0; o >>= 1) {
            if (tid < o) red_sh[tid] += red_sh[tid + o];
            __syncthreads();
        }
        if (tid == 0) {
            out[0] = (float)(red_sh[0] * (1.0 / (double)BATCH));
            g_done = 0;                        // reset for next graph replay
        }
    }
}

extern "C" void kernel_launch(void* const* d_in, const int* in_sizes, int n_in,
                              void* d_out, int out_size)
{
    const float* token_scores = (const float*)d_in[0];
    const void*  tags         = (const void*)d_in[1];
    const int*   token_mask   = (const int*)d_in[2];
    const float* transitions  = (const float*)d_in[3];
    const float* start_trans  = (const float*)d_in[4];
    const float* end_trans    = (const float*)d_in[5];
    float* out = (float*)d_out;

    crf_sched_kernel<<<1, BATCH>>>(token_mask);
    crf_main_kernel<<<NBLK, NTHR>>>(token_scores, tags, token_mask,
                                    transitions, start_trans, end_trans, out);
}

// round 17
// speedup vs baseline: 2.2311x; 1.0792x over previous
#include <cuda_runtime.h>

// Problem constants
#define BATCH 512
#define SEQ   1024
#define NTAG  50
#define TPAD  52          // padded tag count (multiple of 4)
#define BPB   4           // batches per block
#define NBLK  (BATCH / BPB)
#define NTHR  256         // 8 warps: w<4 fwd, w>=4 bwd; wid%4 = SMSP pairing
#define FULLM 0xffffffffu

// Scratch via __device__ globals (no allocs). Counter self-resets each run.
__device__ double g_partial[BATCH];
__device__ int    g_len[BATCH];
__device__ int    g_sched[BATCH];
__device__ unsigned int g_done = 0;

// ----------------------------- f32x2 helpers --------------------------------
typedef unsigned long long u64;

__device__ __forceinline__ u64 pk2(float lo, float hi) {
    u64 r; asm("mov.b64 %0,{%1,%2};" : "=l"(r) : "f"(lo), "f"(hi)); return r;
}
__device__ __forceinline__ void upk2(float& lo, float& hi, u64 v) {
    asm("mov.b64 {%0,%1},%2;" : "=f"(lo), "=f"(hi) : "l"(v));
}
__device__ __forceinline__ u64 fma2_(u64 a, u64 b, u64 c) {
    u64 d; asm("fma.rn.f32x2 %0,%1,%2,%3;" : "=l"(d) : "l"(a), "l"(b), "l"(c)); return d;
}
__device__ __forceinline__ u64 mul2_(u64 a, u64 b) {
    u64 d; asm("mul.rn.f32x2 %0,%1,%2;" : "=l"(d) : "l"(a), "l"(b)); return d;
}
__device__ __forceinline__ u64 add2_(u64 a, u64 b) {
    u64 d; asm("add.rn.f32x2 %0,%1,%2;" : "=l"(d) : "l"(a), "l"(b)); return d;
}

// Accurate expf (init paths needing unbiased rounding): Cody-Waite + Horner.
__device__ __forceinline__ float exp_acc(float x) {
    float n = rintf(x * 1.4426950408889634f);
    float r = fmaf(n, -0.693359375f, x);
    r = fmaf(n, 2.1219444005469057e-4f, r);
    float p = 1.9841270e-4f;
    p = fmaf(p, r, 1.3888889e-3f);
    p = fmaf(p, r, 8.3333333e-3f);
    p = fmaf(p, r, 4.1666668e-2f);
    p = fmaf(p, r, 1.6666667e-1f);
    p = fmaf(p, r, 0.5f);
    p = fmaf(p, r, 1.0f);
    p = fmaf(p, r, 1.0f);
    return p * __int_as_float(((int)n + 127) << 23);
}

// Cheap packed exp for per-step emissions (MUFU.EX2 path, ample accuracy margin).
__device__ __forceinline__ u64 pexpf2(u64 x2) {
    float x0, x1; upk2(x0, x1, x2);
    return pk2(__expf(x0), __expf(x1));
}

// Tags may be int32 (JAX w/o x64 silently downgrades int64) or genuine int64.
__device__ __forceinline__ int get_tag(const void* tags, int b, int t, int mode32) {
    if (mode32) return ((const int*)tags)[b * SEQ + t];
    return (int)((const long long*)tags)[b * SEQ + t];
}

__device__ __forceinline__ float warp_red_f(float v) {
    #pragma unroll
    for (int o = 16; o > 0; o >>= 1) v += __shfl_xor_sync(FULLM, v, o);
    return v;
}
__device__ __forceinline__ double warp_red_d(double v) {
    #pragma unroll
    for (int o = 16; o > 0; o >>= 1) v += __shfl_xor_sync(FULLM, v, o);
    return v;
}

// -------- fused prologue: binary-search lengths + hybrid bitonic sort --------
// mask is a prefix mask (mask[i] = i < len). One block, 512 threads: thread b
// binary-searches the first zero, then an ascending bitonic sort of unique
// (len*1024+tid) keys. Inner steps with j<=16 run as register-resident
// shfl.bfly compare-exchanges (no block barrier); only j>=32 touches SMEM.
__global__ void crf_sched_kernel(const int* __restrict__ mask) {
    __shared__ int keys[BATCH];
    const int tid = threadIdx.x;

    // binary search: first zero index == len (all-ones -> 1024)
    int a = 0, bb = SEQ;
    while (a < bb) {
        int m = (a + bb) >> 1;
        if (__ldg(mask + tid * SEQ + m)) a = m + 1; else bb = m;
    }
    g_len[tid] = a;
    keys[tid] = a * 1024 + tid;
    __syncthreads();

    for (int k = 2; k <= BATCH; k <<= 1) {
        // SMEM phase: cross-warp exchanges (j >= 32), one-sync in-place swap
        for (int j = k >> 1; j >= 32; j >>= 1) {
            int ixj = tid ^ j;
            if (ixj > tid) {
                int x = keys[tid], c = keys[ixj];
                bool up = ((tid & k) == 0);
                if (up ? (x < c) : (x > c)) { keys[tid] = c; keys[ixj] = x; }
            }
            __syncthreads();
        }
        // register phase: intra-warp exchanges (j <= 16) via shfl.bfly
        int key = keys[tid];
        const bool up = ((tid & k) == 0);
        int j0 = (k >> 1) < 16 ? (k >> 1) : 16;
        for (int j = j0; j > 0; j >>= 1) {
            int other = __shfl_xor_sync(FULLM, key, j);
            bool amLower = ((tid & j) == 0);
            key = (up == amLower) ? min(key, other) : max(key, other);
        }
        keys[tid] = key;
        __syncthreads();
    }
    // rank tid -> (block k2, slot q): slots 0/2 take one extreme,
    // slots 1/3 the opposite extreme.
    const int batch = keys[tid] & 1023;
    int k2, q;
    if (tid < 256)       { k2 = tid >> 1;         q = (tid & 1) ? 2 : 0; }
    else if (tid & 1)    { k2 = (511 - tid) >> 1; q = 1; }
    else                 { k2 = (510 - tid) >> 1; q = 3; }
    g_sched[k2 * 4 + q] = batch;
}

// Forward/backward split: den = log sum_i alpha_M[i] * beta_M[i].
// fwd warps (w<4) handle slot w; bwd warps (w>=4) handle slot perm[w-4],
// perm = (1,0,3,2)  =>  each SMSP gets fwd(long)+bwd(short) or vice versa.
// Scaled-linear domain, exact pow2 renorm every 4 steps, emission prefetch 8.
// (Main kernel body byte-identical to the 86.7us R13 version.)
__global__ void __launch_bounds__(NTHR, 1) crf_main_kernel(
    const float* __restrict__ ts,          // [B,S,T] token_scores
    const void*  __restrict__ tags_raw,    // [B,S] int32 OR int64
    const int*   __restrict__ mask,        // [B,S] int32 (prefix mask)
    const float* __restrict__ trans,       // [T,T]
    const float* __restrict__ startt,      // [T]
    const float* __restrict__ endt,        // [T]
    float* __restrict__ out)               // [1]
{
    const int w    = threadIdx.x >> 5;
    const int lane = threadIdx.x & 31;
    const int dir  = w >> 2;                // 0 = fwd, 1 = bwd
    const int bperm[4] = {1, 0, 3, 2};
    const int bq   = (dir == 0) ? (w & 3) : bperm[w & 3];   // slot in block
    const int b    = g_sched[blockIdx.x * BPB + bq];        // scheduled batch
    const int owner = (lane < 25);
    const int j0 = 2 * lane, j1 = 2 * lane + 1;

    __shared__ __align__(16) float afb[BPB][2][TPAD];   // fwd alpha buffers
    __shared__ __align__(16) float cbb[BPB][2][TPAD];   // bwd c buffers
    __shared__ float  betaf[BPB][TPAD];                 // final raw beta_M
    __shared__ float  num_sh[BPB];
    __shared__ int    sEb_sh[BPB];
    __shared__ double red_sh[NTHR];
    __shared__ unsigned int is_last;

    const float* tsb = ts + (size_t)b * SEQ * NTAG;

    const int len = g_len[b];          // >= 1
    const int M   = len >> 1;          // meet point
    const int nb  = len - 1 - M;       // backward step count

    int sumEf = 0, curf = 0;           // fwd state (live only in fwd warps)

    if (dir == 0) {
        // =================== FORWARD WARP ===================
        u64 E0[26], E1[26];
        #pragma unroll
        for (int q = 0; q < 26; q++) {
            float e00 = 0.f, e01 = 0.f, e10 = 0.f, e11 = 0.f;
            if (owner) {
                int i0 = 2 * q, i1 = 2 * q + 1;
                if (i0 < NTAG) {
                    e00 = exp_acc(__ldg(trans + i0 * NTAG + j0));
                    e10 = exp_acc(__ldg(trans + i0 * NTAG + j1));
                }
                if (i1 < NTAG) {
                    e01 = exp_acc(__ldg(trans + i1 * NTAG + j0));
                    e11 = exp_acc(__ldg(trans + i1 * NTAG + j1));
                }
            }
            E0[q] = pk2(e00, e01);
            E1[q] = pk2(e10, e11);
        }

        float* a0f = afb[bq][0];
        float* a1f = afb[bq][1];
        if (owner) {
            a0f[j0] = exp_acc(__ldg(startt + j0) + tsb[j0]);
            a0f[j1] = exp_acc(__ldg(startt + j1) + tsb[j1]);
        }
        if (lane == 25) {
            a0f[50] = 0.f; a0f[51] = 0.f; a1f[50] = 0.f; a1f[51] = 0.f;
        }
        __syncwarp();

        const int lenf = M + 1;        // steps t = 1..M

        u64 xb[8];
        #pragma unroll
        for (int k = 0; k < 8; k++) {
            int t = 1 + k; if (t > SEQ - 1) t = SEQ - 1;
            xb[k] = owner ? __ldg((const u64*)(tsb + (size_t)t * NTAG + j0)) : 0ull;
        }

        auto fstep = [&](u64 ex, bool renorm) {
            const float* af = afb[bq][curf];
            const ulonglong2* av = (const ulonglong2*)af;
            float* an = afb[bq][curf ^ 1];
            if (renorm) {
                int eb = (__float_as_int(af[0]) >> 23) & 255;
                sumEf += eb - 127;
                float fac = __int_as_float((254 - eb) << 23);   // 2^{-e}, exact
                ex = mul2_(ex, pk2(fac, fac));
            }
            u64 c0[4] = {0,0,0,0}, c1[4] = {0,0,0,0};
            #pragma unroll
            for (int q = 0; q < 13; q++) {
                ulonglong2 v = av[q];
                c0[0] = fma2_(v.x, E0[2 * q],     c0[0]);
                c0[q & 1 ? 3 : 1] = fma2_(v.y, E0[2 * q + 1], c0[q & 1 ? 3 : 1]);
                c1[0] = fma2_(v.x, E1[2 * q],     c1[0]);
                c1[q & 1 ? 3 : 1] = fma2_(v.y, E1[2 * q + 1], c1[q & 1 ? 3 : 1]);
            }
            u64 s0 = add2_(add2_(c0[0], c0[1]), c0[3]);
            u64 s1 = add2_(add2_(c1[0], c1[1]), c1[3]);
            float p0, q0, p1, q1;
            upk2(p0, q0, s0); upk2(p1, q1, s1);
            u64 anew = mul2_(pk2(p0 + q0, p1 + q1), ex);
            if (owner) *(u64*)(an + j0) = anew;
            curf ^= 1;
            __syncwarp();
        };

        int tb = 1;
        for (; tb + 7 < lenf; tb += 8) {
            u64 xn[8];
            #pragma unroll
            for (int k = 0; k < 8; k++) {
                int t = tb + 8 + k; if (t > SEQ - 1) t = SEQ - 1;
                xn[k] = owner ? __ldg((const u64*)(tsb + (size_t)t * NTAG + j0)) : 0ull;
            }
            #pragma unroll
            for (int k = 0; k < 8; k++)
                fstep(pexpf2(xb[k]), (k & 3) == 0);
            #pragma unroll
            for (int k = 0; k < 8; k++) xb[k] = xn[k];
        }
        for (int t = tb; t < lenf; t++)
            fstep(pexpf2(xb[t - tb]), (t & 3) == 1);
    } else {
        // =================== BACKWARD WARP ===================
        int any_hi = 0;
        {
            const u64* p64 = (const u64*)tags_raw;
            #pragma unroll
            for (int i = 0; i < 16; i++) any_hi |= (int)(p64[i] >> 32);
        }
        const int mode32 = (any_hi != 0);

        // Numerator (gold-path score).
        float nsum = 0.f;
        for (int t = lane; t < len; t += 32) {
            int tg = get_tag(tags_raw, b, t, mode32);
            nsum += __ldg(tsb + t * NTAG + tg);
            if (t > 0) {
                int tp = get_tag(tags_raw, b, t - 1, mode32);
                nsum += __ldg(trans + tp * NTAG + tg);
            }
        }
        if (lane == 0)
            nsum += __ldg(startt + get_tag(tags_raw, b, 0, mode32))
                  + __ldg(endt   + get_tag(tags_raw, b, len - 1, mode32));
        nsum = warp_red_f(nsum);
        if (lane == 0) num_sh[bq] = nsum;

        int sumEb = 0;

        if (nb == 0) {
            if (owner) {
                betaf[bq][j0] = exp_acc(__ldg(endt + j0));
                betaf[bq][j1] = exp_acc(__ldg(endt + j1));
            }
        } else {
            u64 ER0[26], ER1[26];
            #pragma unroll
            for (int q = 0; q < 26; q++) {
                float e00 = 0.f, e01 = 0.f, e10 = 0.f, e11 = 0.f;
                if (owner) {
                    int c0 = 2 * q, c1 = 2 * q + 1;
                    if (c0 < NTAG) {
                        e00 = exp_acc(__ldg(trans + j0 * NTAG + c0));
                        e10 = exp_acc(__ldg(trans + j1 * NTAG + c0));
                    }
                    if (c1 < NTAG) {
                        e01 = exp_acc(__ldg(trans + j0 * NTAG + c1));
                        e11 = exp_acc(__ldg(trans + j1 * NTAG + c1));
                    }
                }
                ER0[q] = pk2(e00, e01);
                ER1[q] = pk2(e10, e11);
            }

            float* c0f = cbb[bq][0];
            float* c1f = cbb[bq][1];
            if (owner) {   // c_j = exp(x_{len-1}[j] + end_j)
                c0f[j0] = exp_acc(tsb[(size_t)(len - 1) * NTAG + j0] + __ldg(endt + j0));
                c0f[j1] = exp_acc(tsb[(size_t)(len - 1) * NTAG + j1] + __ldg(endt + j1));
            }
            if (lane == 25) {
                c0f[50] = 0.f; c0f[51] = 0.f; c1f[50] = 0.f; c1f[51] = 0.f;
            }
            __syncwarp();

            int curb = 0;
            const int nbm1 = nb - 1;   // normal steps; last step stores raw

            u64 xb[8];
            #pragma unroll
            for (int k = 0; k < 8; k++) {
                int t = len - 2 - k; if (t < 0) t = 0;
                xb[k] = owner ? __ldg((const u64*)(tsb + (size_t)t * NTAG + j0)) : 0ull;
            }

            auto bstep = [&](u64 ex, bool renorm, bool fin) {
                const float* cf = cbb[bq][curb];
                const ulonglong2* cv = (const ulonglong2*)cf;
                float* cn = cbb[bq][curb ^ 1];
                if (renorm) {
                    int eb = (__float_as_int(cf[0]) >> 23) & 255;
                    sumEb += eb - 127;
                    float fac = __int_as_float((254 - eb) << 23);
                    ex = mul2_(ex, pk2(fac, fac));
                }
                u64 c0[4] = {0,0,0,0}, c1[4] = {0,0,0,0};
                #pragma unroll
                for (int q = 0; q < 13; q++) {
                    ulonglong2 v = cv[q];
                    c0[0] = fma2_(v.x, ER0[2 * q],     c0[0]);
                    c0[q & 1 ? 3 : 1] = fma2_(v.y, ER0[2 * q + 1], c0[q & 1 ? 3 : 1]);
                    c1[0] = fma2_(v.x, ER1[2 * q],     c1[0]);
                    c1[q & 1 ? 3 : 1] = fma2_(v.y, ER1[2 * q + 1], c1[q & 1 ? 3 : 1]);
                }
                u64 s0 = add2_(add2_(c0[0], c0[1]), c0[3]);
                u64 s1 = add2_(add2_(c1[0], c1[1]), c1[3]);
                float p0, q0, p1, q1;
                upk2(p0, q0, s0); upk2(p1, q1, s1);
                if (fin) {
                    if (owner) {
                        betaf[bq][j0] = p0 + q0;
                        betaf[bq][j1] = p1 + q1;
                    }
                } else {
                    u64 cnew = mul2_(pk2(p0 + q0, p1 + q1), ex);
                    if (owner) *(u64*)(cn + j0) = cnew;
                }
                curb ^= 1;
                __syncwarp();
            };

            int idx = 0;
            for (; idx + 7 < nbm1; idx += 8) {
                u64 xn[8];
                #pragma unroll
                for (int k = 0; k < 8; k++) {
                    int t = len - 2 - (idx + 8 + k); if (t < 0) t = 0;
                    xn[k] = owner ? __ldg((const u64*)(tsb + (size_t)t * NTAG + j0)) : 0ull;
                }
                #pragma unroll
                for (int k = 0; k < 8; k++)
                    bstep(pexpf2(xb[k]), (k & 3) == 0, false);
                #pragma unroll
                for (int k = 0; k < 8; k++) xb[k] = xn[k];
            }
            for (int k = 0; idx < nbm1; idx++, k++)
                bstep(pexpf2(xb[k]), (idx & 3) == 0, false);

            bstep(0ull, false, true);      // final: store raw beta_M
        }

        if (lane == 0) sEb_sh[bq] = sumEb;
    }

    // ---------------- combine: den = ln2*(sEf+sEb) + log(sum alpha*beta) ----
    __syncthreads();
    if (dir == 0) {
        double part = 0.0;
        if (owner) {
            const float* af = afb[bq][curf];
            part = (double)af[j0] * (double)betaf[bq][j0]
                 + (double)af[j1] * (double)betaf[bq][j1];
        }
        part = warp_red_d(part);
        if (lane == 0) {
            double den = (double)(sumEf + sEb_sh[bq]) * 0.6931471805599453
                       + log(part);
            g_partial[b] = den - (double)num_sh[bq];
        }
    }

    // ---------------- last-block final reduction (deterministic) ----------
    __syncthreads();
    __threadfence();
    if (threadIdx.x == 0)
        is_last = (atomicAdd(&g_done, 1u) == (unsigned)(NBLK - 1));
    __syncthreads();
    if (is_last) {
        const int tid = threadIdx.x;           // 256 threads, 512 partials
        double s = g_partial[tid] + g_partial[tid + NTHR];
        red_sh[tid] = s;
        __syncthreads();
        #pragma unroll
        for (int o = 128; o > 0; o >>= 1) {
            if (tid < o) red_sh[tid] += red_sh[tid + o];
            __syncthreads();
        }
        if (tid == 0) {
            out[0] = (float)(red_sh[0] * (1.0 / (double)BATCH));
            g_done = 0;                        // reset for next graph replay
        }
    }
}

extern "C" void kernel_launch(void* const* d_in, const int* in_sizes, int n_in,
                              void* d_out, int out_size)
{
    const float* token_scores = (const float*)d_in[0];
    const void*  tags         = (const void*)d_in[1];
    const int*   token_mask   = (const int*)d_in[2];
    const float* transitions  = (const float*)d_in[3];
    const float* start_trans  = (const float*)d_in[4];
    const float* end_trans    = (const float*)d_in[5];
    float* out = (float*)d_out;

    crf_sched_kernel<<<1, BATCH>>>(token_mask);
    crf_main_kernel<<<NBLK, NTHR>>>(token_scores, tags, token_mask,
                                    transitions, start_trans, end_trans, out);
}